// round 2
// baseline (speedup 1.0000x reference)
#include <cuda_runtime.h>
#include <cuda_bf16.h>
#include <math.h>

// Problem constants
#define BB   4
#define HH   12
#define TT   2048
#define DD   64
#define PP   768            // H*D
#define SCALE 0.125f        // 1/sqrt(64)

typedef unsigned long long ull;

// ---------------------------------------------------------------------------
// Scratch: Q,K,V in [B,H,T,D] layout (fp32). 3 x 25.2MB static device arrays.
// ---------------------------------------------------------------------------
__device__ float g_q[BB * HH * TT * DD];
__device__ float g_k[BB * HH * TT * DD];
__device__ float g_v[BB * HH * TT * DD];

// ---------------------------------------------------------------------------
// Packed fp32x2 helpers (sm_100+): 2 FMA per instruction on the fma pipe.
// ---------------------------------------------------------------------------
__device__ __forceinline__ ull pack2(float lo, float hi) {
    ull r;
    asm("mov.b64 %0, {%1, %2};" : "=l"(r) : "f"(lo), "f"(hi));
    return r;
}
__device__ __forceinline__ void unpack2(ull v, float& lo, float& hi) {
    asm("mov.b64 {%0, %1}, %2;" : "=f"(lo), "=f"(hi) : "l"(v));
}
__device__ __forceinline__ ull fma2(ull a, ull b, ull c) {
    ull d;
    asm("fma.rn.f32x2 %0, %1, %2, %3;" : "=l"(d) : "l"(a), "l"(b), "l"(c));
    return d;
}
__device__ __forceinline__ ull mul2(ull a, ull b) {
    ull d;
    asm("mul.rn.f32x2 %0, %1, %2;" : "=l"(d) : "l"(a), "l"(b));
    return d;
}

// ---------------------------------------------------------------------------
// Kernel 1: QKV projection.
//   X: [B*T, 64] @ W: [64, 768] + bias -> reshaped into [B,H,T,D] scratch.
//   grid (BT/64, H, 3), 128 threads: 64x64 output tile, 4x8 micro-tile.
// ---------------------------------------------------------------------------
__global__ __launch_bounds__(128)
void qkv_proj_kernel(const float* __restrict__ X,
                     const float* __restrict__ Wq, const float* __restrict__ bq,
                     const float* __restrict__ Wk, const float* __restrict__ bk,
                     const float* __restrict__ Wv, const float* __restrict__ bv) {
    __shared__ float Xs[64][68];   // padded
    __shared__ float Ws[64][64];

    const int rt = blockIdx.x;     // row tile (64 rows of B*T)
    const int h  = blockIdx.y;     // head (column tile of 64)
    const int z  = blockIdx.z;     // 0=q 1=k 2=v

    const float* W    = (z == 0) ? Wq : (z == 1) ? Wk : Wv;
    const float* bias = (z == 0) ? bq : (z == 1) ? bk : bv;
    float* out        = (z == 0) ? g_q : (z == 1) ? g_k : g_v;

    const int tid = threadIdx.x;
    const int ty = tid >> 3;       // 0..15 -> 4-row groups
    const int tx = tid & 7;        // 0..7  -> 8-col groups

    #pragma unroll
    for (int i = 0; i < 8; i++) {
        int lin = i * 512 + tid * 4;         // 4096 floats
        int rr = lin >> 6, kk = lin & 63;
        float4 xv = *(const float4*)(X + (size_t)(rt * 64 + rr) * 64 + kk);
        *(float4*)&Xs[rr][kk] = xv;
        float4 wv = *(const float4*)(W + (size_t)(lin >> 6) * PP + h * 64 + (lin & 63));
        *(float4*)&Ws[lin >> 6][lin & 63] = wv;
    }
    __syncthreads();

    float acc[4][8];
    #pragma unroll
    for (int i = 0; i < 4; i++)
        #pragma unroll
        for (int j = 0; j < 8; j++) acc[i][j] = 0.0f;

    #pragma unroll 4
    for (int k = 0; k < 64; k++) {
        float a[4];
        #pragma unroll
        for (int i = 0; i < 4; i++) a[i] = Xs[ty * 4 + i][k];
        float b[8];
        float4 b0 = *(float4*)&Ws[k][tx * 8];
        float4 b1 = *(float4*)&Ws[k][tx * 8 + 4];
        b[0]=b0.x; b[1]=b0.y; b[2]=b0.z; b[3]=b0.w;
        b[4]=b1.x; b[5]=b1.y; b[6]=b1.z; b[7]=b1.w;
        #pragma unroll
        for (int i = 0; i < 4; i++)
            #pragma unroll
            for (int j = 0; j < 8; j++) acc[i][j] += a[i] * b[j];
    }

    float bb[8];
    #pragma unroll
    for (int j = 0; j < 8; j++) bb[j] = bias[h * 64 + tx * 8 + j];

    #pragma unroll
    for (int i = 0; i < 4; i++) {
        int r = rt * 64 + ty * 4 + i;        // global row in [0, B*T)
        int bidx = r >> 11;                  // / 2048
        int t    = r & 2047;
        float* dst = out + (((size_t)(bidx * HH + h)) * TT + t) * DD + tx * 8;
        float4 o0 = make_float4(acc[i][0]+bb[0], acc[i][1]+bb[1], acc[i][2]+bb[2], acc[i][3]+bb[3]);
        float4 o1 = make_float4(acc[i][4]+bb[4], acc[i][5]+bb[5], acc[i][6]+bb[6], acc[i][7]+bb[7]);
        *(float4*)(dst)     = o0;
        *(float4*)(dst + 4) = o1;
    }
}

// ---------------------------------------------------------------------------
// Kernel 2: flash attention, fp32 with f32x2-packed reduction dims.
//   grid (T/128, B*H), 256 threads. BM=128 queries, BN=64 keys per tile.
//   Thread (ty,tx): ty in [0,16) -> 8 query rows, tx in [0,16) -> 4 cols.
//   K/V tiles for iteration kt+1 are prefetched into registers during
//   iteration kt (issued before the pre-GEMM2 barrier) so global latency
//   hides behind GEMM2.
//   smem (dynamic):
//     Qs [32][128] ull : (Q[r][2kp], Q[r][2kp+1]) pre-scaled       32KB
//     Ks [32][64]  ull : (K[c][2kp], K[c][2kp+1])                  16KB
//     Vs [32][64]  ull : (V[2cp][d], V[2cp+1][d])                  16KB
//     Ps [32][128] ull : (P[r][2cp], P[r][2cp+1])                  32KB
//     ms [64] float    : additive mask                             256B
// ---------------------------------------------------------------------------
#define FLASH_SMEM ((32*128 + 32*64 + 32*64 + 32*128) * 8 + 256)

__global__ __launch_bounds__(256)
void flash_attn_kernel(const float* __restrict__ mask, float* __restrict__ out) {
    extern __shared__ ull sm[];
    ull* Qs = sm;                      // [32][128]
    ull* Ks = Qs + 32 * 128;           // [32][64]
    ull* Vs = Ks + 32 * 64;            // [32][64]
    ull* Ps = Vs + 32 * 64;            // [32][128]
    float* ms = (float*)(Ps + 32 * 128);

    const int qt = blockIdx.x;
    const int bh = blockIdx.y;
    const int b  = bh / HH;
    const int h  = bh % HH;
    const int tid = threadIdx.x;
    const int ty = tid >> 4;           // 0..15
    const int tx = tid & 15;           // 0..15

    const float* qg = g_q + (size_t)bh * TT * DD + (size_t)qt * 128 * DD;
    const float* kg = g_k + (size_t)bh * TT * DD;
    const float* vg = g_v + (size_t)bh * TT * DD;

    // Load Q tile (128x64), scaled, pair-packed k-major: Qs[kp][r]
    #pragma unroll
    for (int i = 0; i < 8; i++) {
        int lin = i * 1024 + tid * 4;      // 8192 floats
        int r  = lin >> 6;
        int kk = lin & 63;
        float4 v = *(const float4*)(qg + lin);
        Qs[(kk >> 1)       * 128 + r] = pack2(v.x * SCALE, v.y * SCALE);
        Qs[((kk >> 1) + 1) * 128 + r] = pack2(v.z * SCALE, v.w * SCALE);
    }

    float m_i[8], l_i[8];
    ull o2[8][4];
    #pragma unroll
    for (int i = 0; i < 8; i++) {
        m_i[i] = -INFINITY;
        l_i[i] = 0.0f;
        #pragma unroll
        for (int j = 0; j < 4; j++) o2[i][j] = 0ull;
    }

    // Prefetch registers for K/V tile (16 floats each per thread)
    float4 kpre[4], vpre[4];
    #pragma unroll
    for (int i = 0; i < 4; i++) {
        int lin = i * 1024 + tid * 4;
        kpre[i] = *(const float4*)(kg + lin);
        vpre[i] = *(const float4*)(vg + lin);
    }

    for (int kt = 0; kt < TT / 64; kt++) {
        __syncthreads();   // previous GEMM2 done before overwriting K/V/Ps

        // Store prefetched K tile (64x64) pair-packed k-major: Ks[kp][c]
        #pragma unroll
        for (int i = 0; i < 4; i++) {
            int lin = i * 1024 + tid * 4;  // 4096 floats
            int c  = lin >> 6;
            int kk = lin & 63;
            float4 v = kpre[i];
            Ks[(kk >> 1)       * 64 + c] = pack2(v.x, v.y);
            Ks[((kk >> 1) + 1) * 64 + c] = pack2(v.z, v.w);
        }
        // Store prefetched V tile (64x64), c-pair-packed: Vs[cp][d]
        {
            float* vsf = (float*)Vs;       // [32][64][2]
            #pragma unroll
            for (int i = 0; i < 4; i++) {
                int lin = i * 1024 + tid * 4;
                int c = lin >> 6;
                int d = lin & 63;
                float4 v = vpre[i];
                int base = ((c >> 1) * 64) * 2 + (c & 1);
                vsf[base + (d + 0) * 2] = v.x;
                vsf[base + (d + 1) * 2] = v.y;
                vsf[base + (d + 2) * 2] = v.z;
                vsf[base + (d + 3) * 2] = v.w;
            }
        }
        if (tid < 64)
            ms[tid] = (1.0f - mask[(size_t)b * TT + kt * 64 + tid]) * -10000.0f;
        __syncthreads();

        // GEMM1: S = Q K^T  (packed over k-pairs)
        ull s2[8][4];
        #pragma unroll
        for (int i = 0; i < 8; i++)
            #pragma unroll
            for (int j = 0; j < 4; j++) s2[i][j] = 0ull;

        #pragma unroll 4
        for (int kp = 0; kp < 32; kp++) {
            const ulonglong2* ap = (const ulonglong2*)(Qs + kp * 128 + ty * 8);
            const ulonglong2* bp = (const ulonglong2*)(Ks + kp * 64 + tx * 4);
            ull a[8], bfr[4];
            ulonglong2 t0 = ap[0], t1 = ap[1], t2 = ap[2], t3 = ap[3];
            a[0]=t0.x; a[1]=t0.y; a[2]=t1.x; a[3]=t1.y;
            a[4]=t2.x; a[5]=t2.y; a[6]=t3.x; a[7]=t3.y;
            ulonglong2 u0 = bp[0], u1 = bp[1];
            bfr[0]=u0.x; bfr[1]=u0.y; bfr[2]=u1.x; bfr[3]=u1.y;
            #pragma unroll
            for (int i = 0; i < 8; i++)
                #pragma unroll
                for (int j = 0; j < 4; j++)
                    s2[i][j] = fma2(a[i], bfr[j], s2[i][j]);
        }

        // reduce pairs, add mask, online softmax
        #pragma unroll
        for (int i = 0; i < 8; i++) {
            float s[4];
            #pragma unroll
            for (int j = 0; j < 4; j++) {
                float lo, hi;
                unpack2(s2[i][j], lo, hi);
                s[j] = lo + hi + ms[tx * 4 + j];
            }
            float tmax = fmaxf(fmaxf(s[0], s[1]), fmaxf(s[2], s[3]));
            #pragma unroll
            for (int off = 1; off < 16; off <<= 1)
                tmax = fmaxf(tmax, __shfl_xor_sync(0xffffffffu, tmax, off));

            float mnew  = fmaxf(m_i[i], tmax);
            float alpha = __expf(m_i[i] - mnew);
            float p[4], psum = 0.0f;
            #pragma unroll
            for (int j = 0; j < 4; j++) { p[j] = __expf(s[j] - mnew); psum += p[j]; }
            #pragma unroll
            for (int off = 1; off < 16; off <<= 1)
                psum += __shfl_xor_sync(0xffffffffu, psum, off);

            l_i[i] = l_i[i] * alpha + psum;
            m_i[i] = mnew;
            ull a2 = pack2(alpha, alpha);
            #pragma unroll
            for (int j = 0; j < 4; j++) o2[i][j] = mul2(o2[i][j], a2);

            // write P, c-pair-packed: Ps[cp][r]
            int r = ty * 8 + i;
            Ps[(tx * 2 + 0) * 128 + r] = pack2(p[0], p[1]);
            Ps[(tx * 2 + 1) * 128 + r] = pack2(p[2], p[3]);
        }

        // Prefetch next K/V tile (hidden behind barrier + GEMM2)
        if (kt + 1 < TT / 64) {
            const float* kn = kg + (size_t)(kt + 1) * 64 * DD;
            const float* vn = vg + (size_t)(kt + 1) * 64 * DD;
            #pragma unroll
            for (int i = 0; i < 4; i++) {
                int lin = i * 1024 + tid * 4;
                kpre[i] = *(const float4*)(kn + lin);
                vpre[i] = *(const float4*)(vn + lin);
            }
        }
        __syncthreads();

        // GEMM2: O += P V  (packed over c-pairs)
        #pragma unroll 4
        for (int cp = 0; cp < 32; cp++) {
            const ulonglong2* ap = (const ulonglong2*)(Ps + cp * 128 + ty * 8);
            const ulonglong2* bp = (const ulonglong2*)(Vs + cp * 64 + tx * 4);
            ull a[8], bfr[4];
            ulonglong2 t0 = ap[0], t1 = ap[1], t2 = ap[2], t3 = ap[3];
            a[0]=t0.x; a[1]=t0.y; a[2]=t1.x; a[3]=t1.y;
            a[4]=t2.x; a[5]=t2.y; a[6]=t3.x; a[7]=t3.y;
            ulonglong2 u0 = bp[0], u1 = bp[1];
            bfr[0]=u0.x; bfr[1]=u0.y; bfr[2]=u1.x; bfr[3]=u1.y;
            #pragma unroll
            for (int i = 0; i < 8; i++)
                #pragma unroll
                for (int j = 0; j < 4; j++)
                    o2[i][j] = fma2(a[i], bfr[j], o2[i][j]);
        }
    }

    // Epilogue: O /= l, write [B,T,H*D]
    #pragma unroll
    for (int i = 0; i < 8; i++) {
        int r = ty * 8 + i;
        int t = qt * 128 + r;
        float inv = 1.0f / l_i[i];
        float res[4];
        #pragma unroll
        for (int j = 0; j < 4; j++) {
            float lo, hi;
            unpack2(o2[i][j], lo, hi);
            res[j] = (lo + hi) * inv;
        }
        float4 v4 = make_float4(res[0], res[1], res[2], res[3]);
        *(float4*)(out + ((size_t)(b * TT + t)) * PP + h * 64 + tx * 4) = v4;
    }
}

// ---------------------------------------------------------------------------
// Launch
// ---------------------------------------------------------------------------
extern "C" void kernel_launch(void* const* d_in, const int* in_sizes, int n_in,
                              void* d_out, int out_size) {
    const float* hs   = (const float*)d_in[0];
    const float* mask = (const float*)d_in[1];
    const float* Wq   = (const float*)d_in[2];
    const float* bq   = (const float*)d_in[3];
    const float* Wk   = (const float*)d_in[4];
    const float* bk   = (const float*)d_in[5];
    const float* Wv   = (const float*)d_in[6];
    const float* bv   = (const float*)d_in[7];
    float* out = (float*)d_out;

    qkv_proj_kernel<<<dim3((BB * TT) / 64, HH, 3), 128>>>(hs, Wq, bq, Wk, bk, Wv, bv);

    cudaFuncSetAttribute(flash_attn_kernel,
                         cudaFuncAttributeMaxDynamicSharedMemorySize, FLASH_SMEM);
    flash_attn_kernel<<<dim3(TT / 128, BB * HH), 256, FLASH_SMEM>>>(mask, out);
}

// round 4
// speedup vs baseline: 1.2525x; 1.2525x over previous
#include <cuda_runtime.h>
#include <cuda_bf16.h>
#include <math.h>

#define BB   4
#define HH   12
#define TT   2048
#define DD   64
#define PP   768
#define SCALE 0.125f

typedef unsigned long long ull;

__device__ float g_q[BB * HH * TT * DD];
__device__ float g_k[BB * HH * TT * DD];
__device__ float g_v[BB * HH * TT * DD];

__device__ __forceinline__ ull pack2(float lo, float hi) {
    ull r;
    asm("mov.b64 %0, {%1, %2};" : "=l"(r) : "f"(lo), "f"(hi));
    return r;
}
__device__ __forceinline__ void unpack2(ull v, float& lo, float& hi) {
    asm("mov.b64 {%0, %1}, %2;" : "=f"(lo), "=f"(hi) : "l"(v));
}
__device__ __forceinline__ ull fma2(ull a, ull b, ull c) {
    ull d;
    asm("fma.rn.f32x2 %0, %1, %2, %3;" : "=l"(d) : "l"(a), "l"(b), "l"(c));
    return d;
}
__device__ __forceinline__ ull mul2(ull a, ull b) {
    ull d;
    asm("mul.rn.f32x2 %0, %1, %2;" : "=l"(d) : "l"(a), "l"(b));
    return d;
}

// ---------------------------------------------------------------------------
// Kernel 1: QKV projection (~4% of runtime)
// ---------------------------------------------------------------------------
__global__ __launch_bounds__(128)
void qkv_proj_kernel(const float* __restrict__ X,
                     const float* __restrict__ Wq, const float* __restrict__ bq,
                     const float* __restrict__ Wk, const float* __restrict__ bk,
                     const float* __restrict__ Wv, const float* __restrict__ bv) {
    __shared__ float Xs[64][68];
    __shared__ float Ws[64][64];

    const int rt = blockIdx.x;
    const int h  = blockIdx.y;
    const int z  = blockIdx.z;

    const float* W    = (z == 0) ? Wq : (z == 1) ? Wk : Wv;
    const float* bias = (z == 0) ? bq : (z == 1) ? bk : bv;
    float* out        = (z == 0) ? g_q : (z == 1) ? g_k : g_v;

    const int tid = threadIdx.x;
    const int ty = tid >> 3;
    const int tx = tid & 7;

    #pragma unroll
    for (int i = 0; i < 8; i++) {
        int lin = i * 512 + tid * 4;
        int rr = lin >> 6, kk = lin & 63;
        float4 xv = *(const float4*)(X + (size_t)(rt * 64 + rr) * 64 + kk);
        *(float4*)&Xs[rr][kk] = xv;
        float4 wv = *(const float4*)(W + (size_t)(lin >> 6) * PP + h * 64 + (lin & 63));
        *(float4*)&Ws[lin >> 6][lin & 63] = wv;
    }
    __syncthreads();

    float acc[4][8];
    #pragma unroll
    for (int i = 0; i < 4; i++)
        #pragma unroll
        for (int j = 0; j < 8; j++) acc[i][j] = 0.0f;

    #pragma unroll 4
    for (int k = 0; k < 64; k++) {
        float a[4];
        #pragma unroll
        for (int i = 0; i < 4; i++) a[i] = Xs[ty * 4 + i][k];
        float b[8];
        float4 b0 = *(float4*)&Ws[k][tx * 8];
        float4 b1 = *(float4*)&Ws[k][tx * 8 + 4];
        b[0]=b0.x; b[1]=b0.y; b[2]=b0.z; b[3]=b0.w;
        b[4]=b1.x; b[5]=b1.y; b[6]=b1.z; b[7]=b1.w;
        #pragma unroll
        for (int i = 0; i < 4; i++)
            #pragma unroll
            for (int j = 0; j < 8; j++) acc[i][j] += a[i] * b[j];
    }

    float bb[8];
    #pragma unroll
    for (int j = 0; j < 8; j++) bb[j] = bias[h * 64 + tx * 8 + j];

    #pragma unroll
    for (int i = 0; i < 4; i++) {
        int r = rt * 64 + ty * 4 + i;
        int bidx = r >> 11;
        int t    = r & 2047;
        float* dst = out + (((size_t)(bidx * HH + h)) * TT + t) * DD + tx * 8;
        float4 o0 = make_float4(acc[i][0]+bb[0], acc[i][1]+bb[1], acc[i][2]+bb[2], acc[i][3]+bb[3]);
        float4 o1 = make_float4(acc[i][4]+bb[4], acc[i][5]+bb[5], acc[i][6]+bb[6], acc[i][7]+bb[7]);
        *(float4*)(dst)     = o0;
        *(float4*)(dst + 4) = o1;
    }
}

// ---------------------------------------------------------------------------
// Kernel 2: flash attention, conflict-free smem layouts.
//   256 threads; ty=tid>>4 (8 query rows each), tx=tid&15.
//   Thread's 4 score columns: {2tx, 2tx+1, 32+2tx, 33+2tx}.
//   Thread's 4 output d-cols:  {4tx..4tx+3}.
//   Layouts:
//     Qs ull [32 kp][130] : (Q[r][2kp],Q[r][2kp+1]) pre-scaled
//     Ks ull [32 kp][66]  : (K[c][2kp],K[c][2kp+1])
//     Vs f32 [64 c][68]   : plain row-major
//     Ps ull [64 c][132]  : duplicated (p,p) pairs, r XOR-swizzled
//     ms f32 [64]
// ---------------------------------------------------------------------------
#define QS_STRIDE 130
#define KS_STRIDE 66
#define VS_STRIDE 68
#define PS_STRIDE 132
#define FLASH_SMEM ((32*QS_STRIDE + 32*KS_STRIDE + 64*PS_STRIDE) * 8 + 64*VS_STRIDE*4 + 256)

__global__ __launch_bounds__(256)
void flash_attn_kernel(const float* __restrict__ mask, float* __restrict__ out) {
    extern __shared__ ull sm[];
    ull*   Qs  = sm;                         // [32][130]
    ull*   Ks  = Qs + 32 * QS_STRIDE;        // [32][66]
    ull*   Ps  = Ks + 32 * KS_STRIDE;        // [64][132]
    float* Vs  = (float*)(Ps + 64 * PS_STRIDE); // [64][68]
    float* ms  = Vs + 64 * VS_STRIDE;        // [64]

    const int qt = blockIdx.x;
    const int bh = blockIdx.y;
    const int b  = bh / HH;
    const int h  = bh % HH;
    const int tid = threadIdx.x;
    const int ty = tid >> 4;                 // 0..15
    const int tx = tid & 15;                 // 0..15

    const float* qg = g_q + (size_t)bh * TT * DD + (size_t)qt * 128 * DD;
    const float* kg = g_k + (size_t)bh * TT * DD;
    const float* vg = g_v + (size_t)bh * TT * DD;

    const int lrow = tid >> 4;
    const int lcol = (tid & 15) * 4;

    // Load Q tile (128x64), scaled, k-pair-major: Qs[kp][r]
    #pragma unroll
    for (int i = 0; i < 8; i++) {
        int r = lrow + i * 16;
        float4 v = *(const float4*)(qg + (size_t)r * DD + lcol);
        int kp = lcol >> 1;
        Qs[(kp    ) * QS_STRIDE + r] = pack2(v.x * SCALE, v.y * SCALE);
        Qs[(kp + 1) * QS_STRIDE + r] = pack2(v.z * SCALE, v.w * SCALE);
    }

    float m_i[8], l_i[8];
    ull o2[8][2];
    #pragma unroll
    for (int i = 0; i < 8; i++) {
        m_i[i] = -INFINITY;
        l_i[i] = 0.0f;
        o2[i][0] = 0ull; o2[i][1] = 0ull;
    }

    // Prefetch K/V tile 0 into registers
    float4 kpre[4], vpre[4];
    #pragma unroll
    for (int i = 0; i < 4; i++) {
        int c = lrow + i * 16;
        kpre[i] = *(const float4*)(kg + (size_t)c * DD + lcol);
        vpre[i] = *(const float4*)(vg + (size_t)c * DD + lcol);
    }

    for (int kt = 0; kt < TT / 64; kt++) {
        __syncthreads();

        // Store K tile: Ks[kp][c] pairs
        #pragma unroll
        for (int i = 0; i < 4; i++) {
            int c = lrow + i * 16;
            int kp = lcol >> 1;
            float4 v = kpre[i];
            Ks[(kp    ) * KS_STRIDE + c] = pack2(v.x, v.y);
            Ks[(kp + 1) * KS_STRIDE + c] = pack2(v.z, v.w);
        }
        // Store V tile: plain row-major float4
        #pragma unroll
        for (int i = 0; i < 4; i++) {
            int c = lrow + i * 16;
            *(float4*)(Vs + c * VS_STRIDE + lcol) = vpre[i];
        }
        if (tid < 64)
            ms[tid] = (1.0f - mask[(size_t)b * TT + kt * 64 + tid]) * -10000.0f;
        __syncthreads();

        // GEMM1: S = Q K^T (f32x2-packed over k-pairs)
        ull s2[8][4];
        #pragma unroll
        for (int i = 0; i < 8; i++)
            #pragma unroll
            for (int j = 0; j < 4; j++) s2[i][j] = 0ull;

        #pragma unroll 4
        for (int kp = 0; kp < 32; kp++) {
            const ull* qrow = Qs + kp * QS_STRIDE + ty * 8;
            const ull* krow = Ks + kp * KS_STRIDE;
            ull a[8], bf[4];
            ulonglong2 t0 = *(const ulonglong2*)(qrow);
            ulonglong2 t1 = *(const ulonglong2*)(qrow + 2);
            ulonglong2 t2 = *(const ulonglong2*)(qrow + 4);
            ulonglong2 t3 = *(const ulonglong2*)(qrow + 6);
            a[0]=t0.x; a[1]=t0.y; a[2]=t1.x; a[3]=t1.y;
            a[4]=t2.x; a[5]=t2.y; a[6]=t3.x; a[7]=t3.y;
            ulonglong2 u0 = *(const ulonglong2*)(krow + 2 * tx);
            ulonglong2 u1 = *(const ulonglong2*)(krow + 32 + 2 * tx);
            bf[0]=u0.x; bf[1]=u0.y; bf[2]=u1.x; bf[3]=u1.y;
            #pragma unroll
            for (int i = 0; i < 8; i++)
                #pragma unroll
                for (int j = 0; j < 4; j++)
                    s2[i][j] = fma2(a[i], bf[j], s2[i][j]);
        }

        // online softmax; columns c0..c3 = 2tx,2tx+1,32+2tx,33+2tx
        const float m0 = ms[2 * tx], m1 = ms[2 * tx + 1];
        const float m2 = ms[32 + 2 * tx], m3 = ms[33 + 2 * tx];
        #pragma unroll
        for (int i = 0; i < 8; i++) {
            float s[4];
            float lo, hi;
            unpack2(s2[i][0], lo, hi); s[0] = lo + hi + m0;
            unpack2(s2[i][1], lo, hi); s[1] = lo + hi + m1;
            unpack2(s2[i][2], lo, hi); s[2] = lo + hi + m2;
            unpack2(s2[i][3], lo, hi); s[3] = lo + hi + m3;

            float tmax = fmaxf(fmaxf(s[0], s[1]), fmaxf(s[2], s[3]));
            #pragma unroll
            for (int off = 1; off < 16; off <<= 1)
                tmax = fmaxf(tmax, __shfl_xor_sync(0xffffffffu, tmax, off));

            float mnew  = fmaxf(m_i[i], tmax);
            float alpha = __expf(m_i[i] - mnew);
            float p0 = __expf(s[0] - mnew);
            float p1 = __expf(s[1] - mnew);
            float p2 = __expf(s[2] - mnew);
            float p3 = __expf(s[3] - mnew);
            l_i[i] = l_i[i] * alpha + (p0 + p1) + (p2 + p3);
            m_i[i] = mnew;
            ull a2 = pack2(alpha, alpha);
            o2[i][0] = mul2(o2[i][0], a2);
            o2[i][1] = mul2(o2[i][1], a2);

            int r = ty * 8 + i;
            int c0 = 2 * tx, c1 = 2 * tx + 1, c2 = 32 + 2 * tx, c3 = 33 + 2 * tx;
            Ps[c0 * PS_STRIDE + (r ^ (((c0 >> 3) & 7) << 2))] = pack2(p0, p0);
            Ps[c1 * PS_STRIDE + (r ^ (((c1 >> 3) & 7) << 2))] = pack2(p1, p1);
            Ps[c2 * PS_STRIDE + (r ^ (((c2 >> 3) & 7) << 2))] = pack2(p2, p2);
            Ps[c3 * PS_STRIDE + (r ^ (((c3 >> 3) & 7) << 2))] = pack2(p3, p3);
        }

        // Prefetch next K/V tile (hidden behind barrier + GEMM2)
        if (kt + 1 < TT / 64) {
            const float* kn = kg + (size_t)(kt + 1) * 64 * DD;
            const float* vn = vg + (size_t)(kt + 1) * 64 * DD;
            #pragma unroll
            for (int i = 0; i < 4; i++) {
                int c = lrow + i * 16;
                kpre[i] = *(const float4*)(kn + (size_t)c * DD + lcol);
                vpre[i] = *(const float4*)(vn + (size_t)c * DD + lcol);
            }
        }
        __syncthreads();

        // GEMM2: O += P V (f32x2-packed over d-pairs; P broadcast, V lane-contiguous)
        #pragma unroll 4
        for (int c = 0; c < 64; c++) {
            int sw = ((c >> 3) & 7) << 2;
            const ull* prow = Ps + c * PS_STRIDE;
            ull pa[8];
            {
                int r0 = ty * 8;
                ulonglong2 q0 = *(const ulonglong2*)(prow + ((r0 + 0) ^ sw));
                ulonglong2 q1 = *(const ulonglong2*)(prow + ((r0 + 2) ^ sw));
                ulonglong2 q2 = *(const ulonglong2*)(prow + ((r0 + 4) ^ sw));
                ulonglong2 q3 = *(const ulonglong2*)(prow + ((r0 + 6) ^ sw));
                pa[0]=q0.x; pa[1]=q0.y; pa[2]=q1.x; pa[3]=q1.y;
                pa[4]=q2.x; pa[5]=q2.y; pa[6]=q3.x; pa[7]=q3.y;
            }
            ulonglong2 vp = *(const ulonglong2*)(Vs + c * VS_STRIDE + 4 * tx);
            #pragma unroll
            for (int i = 0; i < 8; i++) {
                o2[i][0] = fma2(pa[i], vp.x, o2[i][0]);
                o2[i][1] = fma2(pa[i], vp.y, o2[i][1]);
            }
        }
    }

    // Epilogue: reduce l across the 16 lanes of each row group, scale, store.
    #pragma unroll
    for (int i = 0; i < 8; i++) {
        float lsum = l_i[i];
        #pragma unroll
        for (int off = 1; off < 16; off <<= 1)
            lsum += __shfl_xor_sync(0xffffffffu, lsum, off);
        float inv = 1.0f / lsum;
        float a0, a1, a2v, a3;
        unpack2(o2[i][0], a0, a1);
        unpack2(o2[i][1], a2v, a3);
        int r = ty * 8 + i;
        int t = qt * 128 + r;
        float4 v4 = make_float4(a0 * inv, a1 * inv, a2v * inv, a3 * inv);
        *(float4*)(out + ((size_t)(b * TT + t)) * PP + h * 64 + 4 * tx) = v4;
    }
}

// ---------------------------------------------------------------------------
extern "C" void kernel_launch(void* const* d_in, const int* in_sizes, int n_in,
                              void* d_out, int out_size) {
    const float* hs   = (const float*)d_in[0];
    const float* mask = (const float*)d_in[1];
    const float* Wq   = (const float*)d_in[2];
    const float* bq   = (const float*)d_in[3];
    const float* Wk   = (const float*)d_in[4];
    const float* bk   = (const float*)d_in[5];
    const float* Wv   = (const float*)d_in[6];
    const float* bv   = (const float*)d_in[7];
    float* out = (float*)d_out;

    qkv_proj_kernel<<<dim3((BB * TT) / 64, HH, 3), 128>>>(hs, Wq, bq, Wk, bk, Wv, bv);

    cudaFuncSetAttribute(flash_attn_kernel,
                         cudaFuncAttributeMaxDynamicSharedMemorySize, FLASH_SMEM);
    flash_attn_kernel<<<dim3(TT / 128, BB * HH), 256, FLASH_SMEM>>>(mask, out);
}